// round 9
// baseline (speedup 1.0000x reference)
#include <cuda_runtime.h>
#include <math.h>

#define NB 16
#define NH 32
#define NKVH 8
#define ND 128
#define NS 4096
#define NG 4
#define NSPLIT 64
#define CHUNK 64
#define TILE 64
// score domain = log2: q pre-scaled by (1/sqrt(128)) * log2(e)
#define QSCALE (0.08838834764831845f * 1.4426950408889634f)

typedef unsigned long long u64;

// Static device scratch (no allocation allowed).
__device__ float g_acc[(size_t)NB * NH * NSPLIT * ND];  // 16.7 MB
__device__ float g_m[NB * NH * NSPLIT];                 // log2-domain maxima
__device__ float g_l[NB * NH * NSPLIT];

__device__ __forceinline__ float ex2(float x)
{
    float y;
    asm("ex2.approx.f32 %0, %1;" : "=f"(y) : "f"(x));
    return y;
}

// Packed f32x2 helpers (SASS FFMA2/FMUL2 — only reachable via PTX f32x2 ops).
__device__ __forceinline__ u64 packdup(float x)
{
    unsigned xi = __float_as_uint(x);
    u64 r;
    asm("mov.b64 %0, {%1, %2};" : "=l"(r) : "r"(xi), "r"(xi));
    return r;
}
__device__ __forceinline__ u64 fma2(u64 a, u64 b, u64 c)
{
    u64 d;
    asm("fma.rn.f32x2 %0, %1, %2, %3;" : "=l"(d) : "l"(a), "l"(b), "l"(c));
    return d;
}
__device__ __forceinline__ u64 mul2(u64 a, u64 b)
{
    u64 d;
    asm("mul.rn.f32x2 %0, %1, %2;" : "=l"(d) : "l"(a), "l"(b));
    return d;
}

// Score for one key: RoPE(K) dot q for 4 heads; after the interleaved
// 6-shuffle reduction, lane l holds the COMPLETE score of head (l&3),
// already in log2 domain (q carries QSCALE).
__device__ __forceinline__ float score_key(
    float4 cc, float2 kA, float2 kB, int lane,
    const float* qlx, const float* qly, const float* qhx, const float* qhy)
{
    float r0 = kA.x * cc.x - kB.x * cc.z;
    float r1 = kA.y * cc.y - kB.y * cc.w;
    float r2 = kB.x * cc.x + kA.x * cc.z;
    float r3 = kB.y * cc.y + kA.y * cc.w;

    float d0 = qlx[0] * r0 + qly[0] * r1 + qhx[0] * r2 + qhy[0] * r3;
    float d1 = qlx[1] * r0 + qly[1] * r1 + qhx[1] * r2 + qhy[1] * r3;
    float d2 = qlx[2] * r0 + qly[2] * r1 + qhx[2] * r2 + qhy[2] * r3;
    float d3 = qlx[3] * r0 + qly[3] * r1 + qhx[3] * r2 + qhy[3] * r3;

    float s1  = (lane & 1) ? d0 : d1;
    float e01 = ((lane & 1) ? d1 : d0) + __shfl_xor_sync(0xffffffffu, s1, 1);
    float s2  = (lane & 1) ? d2 : d3;
    float e23 = ((lane & 1) ? d3 : d2) + __shfl_xor_sync(0xffffffffu, s2, 1);
    float s3  = (lane & 2) ? e01 : e23;
    float f   = ((lane & 2) ? e23 : e01) + __shfl_xor_sync(0xffffffffu, s3, 2);
    f += __shfl_xor_sync(0xffffffffu, f, 4);
    f += __shfl_xor_sync(0xffffffffu, f, 8);
    f += __shfl_xor_sync(0xffffffffu, f, 16);
    return f;
}

// ---------------------------------------------------------------------------
// Main split-KV kernel. CTA = (split, batch); warp = kv head.
// ---------------------------------------------------------------------------
__global__ __launch_bounds__(256, 2)
void pa_partial_kernel(const float* __restrict__ query,
                       const float* __restrict__ k_cache,
                       const float* __restrict__ v_cache,
                       const int*   __restrict__ slots,
                       const int*   __restrict__ positions,
                       const int*   __restrict__ ctx_lens)
{
    __shared__ float4 cs[TILE][32];   // rope factors: 32 KB
    __shared__ int    slot_sh[TILE];

    const int split = blockIdx.x;
    const int b     = blockIdx.y;
    const int tid   = threadIdx.x;
    const int w     = tid >> 5;       // warp = kv head
    const int lane  = tid & 31;

    const int ctx     = ctx_lens[b];
    const int s_begin = split * CHUNK;

    if (s_begin >= ctx) return;       // empty split: combine skips it entirely
    const int n = min(ctx - s_begin, CHUNK);

    // inv_freq for this lane's pair — fp64, once per thread (noise-level cost).
    const float inv0 = (float)exp(-9.210340371976184 * (double)(2 * lane)     / 64.0);
    const float inv1 = (float)exp(-9.210340371976184 * (double)(2 * lane + 1) / 64.0);

    // ---- cooperative fill: slots + rope factors (sincos once per (b,s)) ----
    if (tid < n) slot_sh[tid] = slots[b * NS + s_begin + tid];
    for (int key = w; key < n; key += 8) {
        float p = (float)positions[b * NS + s_begin + key];
        float fs0, fc0, fs1, fc1;
        sincosf(p * inv0, &fs0, &fc0);
        sincosf(p * inv1, &fs1, &fc1);
        cs[key][lane] = make_float4(fc0, fc1, fs0, fs1);
    }

    // ---- RoPE'd + log2-scaled query (4 heads) in registers ----
    float qlx[NG], qly[NG], qhx[NG], qhy[NG];
    {
        const int pos_last = positions[b * NS + ctx - 1];
        float sn0, cn0, sn1, cn1;
        sincosf((float)pos_last * inv0, &sn0, &cn0);
        sincosf((float)pos_last * inv1, &sn1, &cn1);
#pragma unroll
        for (int g = 0; g < NG; g++) {
            const float* qp = query + (size_t)(b * NH + w * NG + g) * ND;
            float2 a  = *(const float2*)(qp + 2 * lane);
            float2 bb = *(const float2*)(qp + 2 * lane + 64);
            qlx[g] = (a.x * cn0 - bb.x * sn0) * QSCALE;
            qly[g] = (a.y * cn1 - bb.y * sn1) * QSCALE;
            qhx[g] = (bb.x * cn0 + a.x * sn0) * QSCALE;
            qhy[g] = (bb.y * cn1 + a.y * sn1) * QSCALE;
        }
    }

    // Distributed softmax state: lane l tracks m/l of head (l&3), log2 domain.
    // Accumulators packed as f32x2: accA = dims(4l,4l+1), accB = dims(4l+2,4l+3).
    float mL = -1e30f, lL = 0.f;
    u64 accA[NG], accB[NG];
#pragma unroll
    for (int g = 0; g < NG; g++) { accA[g] = 0ull; accB[g] = 0ull; }

    __syncthreads();

    const float* kb = k_cache + w * ND;
    const float* vb = v_cache + w * ND;

    float2 kA0[4], kB0[4], kA1[4], kB1[4];
    ulonglong2 v0[4], v1[4];           // V rows pre-packed as 2×f32x2

#define LOADG(KA, KB, VV, base)                                         \
    {                                                                   \
        _Pragma("unroll")                                               \
        for (int j = 0; j < 4; j++) {                                   \
            int sl_ = slot_sh[(base) + j];                              \
            const float* kr_ = kb + ((size_t)sl_ << 10);                \
            const float* vr_ = vb + ((size_t)sl_ << 10);                \
            KA[j] = *(const float2*)(kr_ + 2 * lane);                   \
            KB[j] = *(const float2*)(kr_ + 2 * lane + 64);              \
            VV[j] = *(const ulonglong2*)(vr_ + 4 * lane);               \
        }                                                               \
    }

#define LOADG_C(KA, KB, VV, base)                                       \
    {                                                                   \
        _Pragma("unroll")                                               \
        for (int j = 0; j < 4; j++) {                                   \
            int sl_ = slot_sh[min((base) + j, n - 1)];                  \
            const float* kr_ = kb + ((size_t)sl_ << 10);                \
            const float* vr_ = vb + ((size_t)sl_ << 10);                \
            KA[j] = *(const float2*)(kr_ + 2 * lane);                   \
            KB[j] = *(const float2*)(kr_ + 2 * lane + 64);              \
            VV[j] = *(const ulonglong2*)(vr_ + 4 * lane);               \
        }                                                               \
    }

#define PROCG(KA, KB, VV, base, MASKED)                                 \
    {                                                                   \
        float sc0 = score_key(cs[(base) + 0][lane], KA[0], KB[0], lane, qlx, qly, qhx, qhy); \
        float sc1 = score_key(cs[(base) + 1 < TILE ? (base) + 1 : 0][lane], KA[1], KB[1], lane, qlx, qly, qhx, qhy); \
        float sc2 = score_key(cs[(base) + 2 < TILE ? (base) + 2 : 0][lane], KA[2], KB[2], lane, qlx, qly, qhx, qhy); \
        float sc3 = score_key(cs[(base) + 3 < TILE ? (base) + 3 : 0][lane], KA[3], KB[3], lane, qlx, qly, qhx, qhy); \
        if (MASKED) {                                                   \
            if ((base) + 1 >= n) sc1 = -1e30f;                          \
            if ((base) + 2 >= n) sc2 = -1e30f;                          \
            if ((base) + 3 >= n) sc3 = -1e30f;                          \
        }                                                               \
        float gmax = fmaxf(fmaxf(sc0, sc1), fmaxf(sc2, sc3));           \
        float mn   = fmaxf(mL, gmax);                                   \
        float corr = ex2(mL - mn);                                      \
        mL = mn;                                                        \
        lL *= corr;                                                     \
        {                                                               \
            u64 cp0 = packdup(__shfl_sync(0xffffffffu, corr, 0));       \
            u64 cp1 = packdup(__shfl_sync(0xffffffffu, corr, 1));       \
            u64 cp2 = packdup(__shfl_sync(0xffffffffu, corr, 2));       \
            u64 cp3 = packdup(__shfl_sync(0xffffffffu, corr, 3));       \
            accA[0] = mul2(accA[0], cp0); accB[0] = mul2(accB[0], cp0); \
            accA[1] = mul2(accA[1], cp1); accB[1] = mul2(accB[1], cp1); \
            accA[2] = mul2(accA[2], cp2); accB[2] = mul2(accB[2], cp2); \
            accA[3] = mul2(accA[3], cp3); accB[3] = mul2(accB[3], cp3); \
        }                                                               \
        _Pragma("unroll")                                               \
        for (int j = 0; j < 4; j++) {                                   \
            float scj = (j == 0) ? sc0 : (j == 1) ? sc1 : (j == 2) ? sc2 : sc3; \
            float wv  = ex2(scj - mn);                                  \
            lL += wv;                                                   \
            u64 w0 = packdup(__shfl_sync(0xffffffffu, wv, 0));          \
            u64 w1 = packdup(__shfl_sync(0xffffffffu, wv, 1));          \
            u64 w2 = packdup(__shfl_sync(0xffffffffu, wv, 2));          \
            u64 w3 = packdup(__shfl_sync(0xffffffffu, wv, 3));          \
            ulonglong2 vj = VV[j];                                      \
            accA[0] = fma2(w0, vj.x, accA[0]); accB[0] = fma2(w0, vj.y, accB[0]); \
            accA[1] = fma2(w1, vj.x, accA[1]); accB[1] = fma2(w1, vj.y, accB[1]); \
            accA[2] = fma2(w2, vj.x, accA[2]); accB[2] = fma2(w2, vj.y, accB[2]); \
            accA[3] = fma2(w3, vj.x, accA[3]); accB[3] = fma2(w3, vj.y, accB[3]); \
        }                                                               \
    }

    if (n == CHUNK) {
        // Clean path: 16 full groups, double-buffered, no clamps/masks.
        LOADG(kA0, kB0, v0, 0);
#pragma unroll 1
        for (int base = 0; base < CHUNK; base += 8) {
            LOADG(kA1, kB1, v1, base + 4);
            PROCG(kA0, kB0, v0, base, 0);
            if (base + 8 < CHUNK) LOADG(kA0, kB0, v0, base + 8);
            PROCG(kA1, kB1, v1, base + 4, 0);
        }
    } else {
        // Ragged path (<= 1 CTA per batch): clamped loads + masked scores.
        LOADG_C(kA0, kB0, v0, 0);
#pragma unroll 1
        for (int base = 0; base < n; base += 8) {
            if (base + 4 < n) LOADG_C(kA1, kB1, v1, base + 4);
            PROCG(kA0, kB0, v0, base, 1);
            if (base + 4 < n) {
                if (base + 8 < n) LOADG_C(kA0, kB0, v0, base + 8);
                PROCG(kA1, kB1, v1, base + 4, 1);
            }
        }
    }
#undef LOADG
#undef LOADG_C
#undef PROCG

    // ---- write split partials (m in log2 domain; acc stored packed) ----
#pragma unroll
    for (int g = 0; g < NG; g++) {
        size_t p = (size_t)(b * NH + w * NG + g) * NSPLIT + split;
        ulonglong2 st; st.x = accA[g]; st.y = accB[g];
        *(ulonglong2*)(g_acc + p * ND + 4 * lane) = st;
    }
    if (lane < NG) {
        size_t p = (size_t)(b * NH + w * NG + lane) * NSPLIT + split;
        g_m[p] = mL; g_l[p] = lL;
    }
}

// ---------------------------------------------------------------------------
// Combine: only the ceil(ctx/64) ACTIVE splits are read (avg ~32 of 64).
// ---------------------------------------------------------------------------
__global__ __launch_bounds__(512)
void pa_combine_kernel(float* __restrict__ out, const int* __restrict__ ctx_lens)
{
    __shared__ float msh[NSPLIT], lsh[NSPLIT];
    __shared__ float osh[4][ND];

    const int bh  = blockIdx.x;          // b*NH + h
    const int tid = threadIdx.x;
    const int d   = tid & (ND - 1);
    const int j   = tid >> 7;            // 0..3

    const int ctx  = ctx_lens[bh >> 5];
    const int nact = (ctx + CHUNK - 1) >> 6;   // active splits, >=1

    if (tid < NSPLIT) {
        bool a = tid < nact;
        msh[tid] = a ? g_m[(size_t)bh * NSPLIT + tid] : -1e30f;
        lsh[tid] = a ? g_l[(size_t)bh * NSPLIT + tid] : 0.f;
    }
    __syncthreads();

    float M = -1e30f;
#pragma unroll
    for (int s = 0; s < NSPLIT; s++) M = fmaxf(M, msh[s]);

    float L = 0.f;
#pragma unroll
    for (int s = 0; s < NSPLIT; s++) L += ex2(msh[s] - M) * lsh[s];

    const int q  = (nact + 3) >> 2;
    const int s0 = j * q;
    const int s1 = min(nact, s0 + q);
    float o = 0.f;
#pragma unroll 4
    for (int s = s0; s < s1; s++)
        o += ex2(msh[s] - M) * g_acc[((size_t)bh * NSPLIT + s) * ND + d];

    osh[j][d] = o;
    __syncthreads();
    if (j == 0)
        out[(size_t)bh * ND + d] =
            (osh[0][d] + osh[1][d] + osh[2][d] + osh[3][d]) / L;
}

// Empty kernel appended so ncu's fixed skip lands on pa_partial_kernel.
__global__ void pa_dummy_kernel() {}

extern "C" void kernel_launch(void* const* d_in, const int* in_sizes, int n_in,
                              void* d_out, int out_size)
{
    const float* query     = (const float*)d_in[0];
    const float* k_cache   = (const float*)d_in[1];
    const float* v_cache   = (const float*)d_in[2];
    const int*   slots     = (const int*)d_in[3];
    const int*   positions = (const int*)d_in[4];
    const int*   ctx_lens  = (const int*)d_in[5];
    float*       out       = (float*)d_out;

    dim3 grid(NSPLIT, NB);
    pa_partial_kernel<<<grid, 256>>>(query, k_cache, v_cache, slots, positions, ctx_lens);
    pa_combine_kernel<<<NB * NH, 512>>>(out, ctx_lens);
    pa_dummy_kernel<<<1, 32>>>();
}

// round 11
// speedup vs baseline: 1.0257x; 1.0257x over previous
#include <cuda_runtime.h>
#include <math.h>

#define NB 16
#define NH 32
#define NKVH 8
#define ND 128
#define NS 4096
#define NG 4
#define NSPLIT 64
#define CHUNK 64
#define TILE 64
// score domain = log2: q pre-scaled by (1/sqrt(128)) * log2(e)
#define QSCALE (0.08838834764831845f * 1.4426950408889634f)

typedef unsigned long long u64;

// Static device scratch (no allocation allowed). Zero-initialized at load.
__device__ float g_acc[(size_t)NB * NH * NSPLIT * ND];  // 16.7 MB
__device__ float g_m[NB * NH * NSPLIT];                 // log2-domain maxima
__device__ float g_l[NB * NH * NSPLIT];

// Dynamic smem layout (bytes):
//   [0, 32768)          cs: rope factors float4[TILE][32]
//   [32768, 33024)      slot_sh: int[64]
//   [33024, 98560)      stage: 2 buffers x 4 keys x 8KB (K 4KB + V 4KB)
#define CS_BYTES   (TILE * 32 * 16)
#define SLOT_OFF   CS_BYTES
#define STAGE_OFF  (CS_BYTES + 256)
#define KEY_FLOATS 2048
#define STAGE_KEYS 4
#define SMEM_TOTAL (STAGE_OFF + 2 * STAGE_KEYS * KEY_FLOATS * 4)   // 98560

__device__ __forceinline__ float ex2(float x)
{
    float y;
    asm("ex2.approx.f32 %0, %1;" : "=f"(y) : "f"(x));
    return y;
}

// Packed f32x2 helpers (SASS FFMA2/FMUL2 via PTX f32x2 ops).
__device__ __forceinline__ u64 packdup(float x)
{
    unsigned xi = __float_as_uint(x);
    u64 r;
    asm("mov.b64 %0, {%1, %2};" : "=l"(r) : "r"(xi), "r"(xi));
    return r;
}
__device__ __forceinline__ u64 fma2(u64 a, u64 b, u64 c)
{
    u64 d;
    asm("fma.rn.f32x2 %0, %1, %2, %3;" : "=l"(d) : "l"(a), "l"(b), "l"(c));
    return d;
}
__device__ __forceinline__ u64 mul2(u64 a, u64 b)
{
    u64 d;
    asm("mul.rn.f32x2 %0, %1, %2;" : "=l"(d) : "l"(a), "l"(b));
    return d;
}

// Score for one key: RoPE(K) dot q for 4 heads; after the interleaved
// 6-shuffle reduction, lane l holds the COMPLETE score of head (l&3).
__device__ __forceinline__ float score_key(
    float4 cc, float2 kA, float2 kB, int lane,
    const float* qlx, const float* qly, const float* qhx, const float* qhy)
{
    float r0 = kA.x * cc.x - kB.x * cc.z;
    float r1 = kA.y * cc.y - kB.y * cc.w;
    float r2 = kB.x * cc.x + kA.x * cc.z;
    float r3 = kB.y * cc.y + kA.y * cc.w;

    float d0 = qlx[0] * r0 + qly[0] * r1 + qhx[0] * r2 + qhy[0] * r3;
    float d1 = qlx[1] * r0 + qly[1] * r1 + qhx[1] * r2 + qhy[1] * r3;
    float d2 = qlx[2] * r0 + qly[2] * r1 + qhx[2] * r2 + qhy[2] * r3;
    float d3 = qlx[3] * r0 + qly[3] * r1 + qhx[3] * r2 + qhy[3] * r3;

    float s1  = (lane & 1) ? d0 : d1;
    float e01 = ((lane & 1) ? d1 : d0) + __shfl_xor_sync(0xffffffffu, s1, 1);
    float s2  = (lane & 1) ? d2 : d3;
    float e23 = ((lane & 1) ? d3 : d2) + __shfl_xor_sync(0xffffffffu, s2, 1);
    float s3  = (lane & 2) ? e01 : e23;
    float f   = ((lane & 2) ? e23 : e01) + __shfl_xor_sync(0xffffffffu, s3, 2);
    f += __shfl_xor_sync(0xffffffffu, f, 4);
    f += __shfl_xor_sync(0xffffffffu, f, 8);
    f += __shfl_xor_sync(0xffffffffu, f, 16);
    return f;
}

// ---------------------------------------------------------------------------
// Main split-KV kernel. CTA = (split, batch); warp = kv head.
// K/V staged through smem with cp.async: whole 4KB slot rows, CTA-cooperative.
// ---------------------------------------------------------------------------
__global__ __launch_bounds__(256, 2)
void pa_partial_kernel(const float* __restrict__ query,
                       const float* __restrict__ k_cache,
                       const float* __restrict__ v_cache,
                       const int*   __restrict__ slots,
                       const int*   __restrict__ positions,
                       const int*   __restrict__ ctx_lens)
{
    extern __shared__ char smem[];
    float4* cs      = (float4*)smem;                 // [TILE*32]
    int*    slot_sh = (int*)(smem + SLOT_OFF);
    float*  stage   = (float*)(smem + STAGE_OFF);

    const int split = blockIdx.x;
    const int b     = blockIdx.y;
    const int tid   = threadIdx.x;
    const int w     = tid >> 5;       // warp = kv head
    const int lane  = tid & 31;

    const int ctx     = ctx_lens[b];
    const int s_begin = split * CHUNK;

    if (s_begin >= ctx) return;       // empty split: combine zero-gates it
    const int n = min(ctx - s_begin, CHUNK);

    if (tid < n) slot_sh[tid] = slots[b * NS + s_begin + tid];
    __syncthreads();                  // slot_sh visible to all fills

    const unsigned st_base = (unsigned)__cvta_generic_to_shared(stage);

    // CTA-cooperative stage fill: per key, 256 threads x 16B = 4KB K + 4KB V.
#define FILLG(buf, base)                                                \
    {                                                                   \
        _Pragma("unroll")                                               \
        for (int j = 0; j < 4; j++) {                                   \
            int key_ = min((base) + j, n - 1);                          \
            size_t sl_ = (size_t)slot_sh[key_];                         \
            unsigned sk = st_base + ((buf) * STAGE_KEYS + j) * (KEY_FLOATS * 4) + tid * 16; \
            const char* gk = (const char*)k_cache + (sl_ << 12) + tid * 16; \
            const char* gv = (const char*)v_cache + (sl_ << 12) + tid * 16; \
            asm volatile("cp.async.cg.shared.global [%0], [%1], 16;" :: "r"(sk) , "l"(gk)); \
            asm volatile("cp.async.cg.shared.global [%0], [%1], 16;" :: "r"(sk + 4096), "l"(gv)); \
        }                                                               \
        asm volatile("cp.async.commit_group;");                         \
    }

    // Prologue: both buffers in flight while we do sincos work below.
    FILLG(0, 0);
    FILLG(1, 4);

    // inv_freq for this lane's pair — fp64, once per thread (noise-level cost).
    const float inv0 = (float)exp(-9.210340371976184 * (double)(2 * lane)     / 64.0);
    const float inv1 = (float)exp(-9.210340371976184 * (double)(2 * lane + 1) / 64.0);

    // ---- rope factors (sincos once per (b,s)), overlapped with cp.async ----
    for (int key = w; key < n; key += 8) {
        float p = (float)positions[b * NS + s_begin + key];
        float fs0, fc0, fs1, fc1;
        sincosf(p * inv0, &fs0, &fc0);
        sincosf(p * inv1, &fs1, &fc1);
        cs[key * 32 + lane] = make_float4(fc0, fc1, fs0, fs1);
    }

    // ---- RoPE'd + log2-scaled query (4 heads) in registers ----
    float qlx[NG], qly[NG], qhx[NG], qhy[NG];
    {
        const int pos_last = positions[b * NS + ctx - 1];
        float sn0, cn0, sn1, cn1;
        sincosf((float)pos_last * inv0, &sn0, &cn0);
        sincosf((float)pos_last * inv1, &sn1, &cn1);
#pragma unroll
        for (int g = 0; g < NG; g++) {
            const float* qp = query + (size_t)(b * NH + w * NG + g) * ND;
            float2 a  = *(const float2*)(qp + 2 * lane);
            float2 bb = *(const float2*)(qp + 2 * lane + 64);
            qlx[g] = (a.x * cn0 - bb.x * sn0) * QSCALE;
            qly[g] = (a.y * cn1 - bb.y * sn1) * QSCALE;
            qhx[g] = (bb.x * cn0 + a.x * sn0) * QSCALE;
            qhy[g] = (bb.y * cn1 + a.y * sn1) * QSCALE;
        }
    }

    // Distributed softmax state: lane l tracks m/l of head (l&3), log2 domain.
    float mL = -1e30f, lL = 0.f;
    u64 accA[NG], accB[NG];
#pragma unroll
    for (int g = 0; g < NG; g++) { accA[g] = 0ull; accB[g] = 0ull; }

    __syncthreads();                  // cs visible

    // Process 4 staged keys from smem (conflict-free LDS), group softmax.
#define PROCG_S(buf, base, MASKED)                                      \
    {                                                                   \
        float2 kA[4], kB[4];                                            \
        ulonglong2 vv[4];                                               \
        _Pragma("unroll")                                               \
        for (int j = 0; j < 4; j++) {                                   \
            const float* kf = stage + ((buf) * STAGE_KEYS + j) * KEY_FLOATS + w * 128; \
            kA[j] = *(const float2*)(kf + 2 * lane);                    \
            kB[j] = *(const float2*)(kf + 2 * lane + 64);               \
            vv[j] = *(const ulonglong2*)(kf + 1024 + 4 * lane);         \
        }                                                               \
        float sc0 = score_key(cs[((base) + 0) * 32 + lane], kA[0], kB[0], lane, qlx, qly, qhx, qhy); \
        float sc1 = score_key(cs[(((base) + 1) & (TILE - 1)) * 32 + lane], kA[1], kB[1], lane, qlx, qly, qhx, qhy); \
        float sc2 = score_key(cs[(((base) + 2) & (TILE - 1)) * 32 + lane], kA[2], kB[2], lane, qlx, qly, qhx, qhy); \
        float sc3 = score_key(cs[(((base) + 3) & (TILE - 1)) * 32 + lane], kA[3], kB[3], lane, qlx, qly, qhx, qhy); \
        if (MASKED) {                                                   \
            if ((base) + 1 >= n) sc1 = -1e30f;                          \
            if ((base) + 2 >= n) sc2 = -1e30f;                          \
            if ((base) + 3 >= n) sc3 = -1e30f;                          \
        }                                                               \
        float gmax = fmaxf(fmaxf(sc0, sc1), fmaxf(sc2, sc3));           \
        float mn   = fmaxf(mL, gmax);                                   \
        float corr = ex2(mL - mn);                                      \
        mL = mn;                                                        \
        lL *= corr;                                                     \
        {                                                               \
            u64 cp0 = packdup(__shfl_sync(0xffffffffu, corr, 0));       \
            u64 cp1 = packdup(__shfl_sync(0xffffffffu, corr, 1));       \
            u64 cp2 = packdup(__shfl_sync(0xffffffffu, corr, 2));       \
            u64 cp3 = packdup(__shfl_sync(0xffffffffu, corr, 3));       \
            accA[0] = mul2(accA[0], cp0); accB[0] = mul2(accB[0], cp0); \
            accA[1] = mul2(accA[1], cp1); accB[1] = mul2(accB[1], cp1); \
            accA[2] = mul2(accA[2], cp2); accB[2] = mul2(accB[2], cp2); \
            accA[3] = mul2(accA[3], cp3); accB[3] = mul2(accB[3], cp3); \
        }                                                               \
        _Pragma("unroll")                                               \
        for (int j = 0; j < 4; j++) {                                   \
            float scj = (j == 0) ? sc0 : (j == 1) ? sc1 : (j == 2) ? sc2 : sc3; \
            float wv2 = ex2(scj - mn);                                  \
            lL += wv2;                                                  \
            u64 w0 = packdup(__shfl_sync(0xffffffffu, wv2, 0));         \
            u64 w1 = packdup(__shfl_sync(0xffffffffu, wv2, 1));         \
            u64 w2 = packdup(__shfl_sync(0xffffffffu, wv2, 2));         \
            u64 w3 = packdup(__shfl_sync(0xffffffffu, wv2, 3));         \
            ulonglong2 vj = vv[j];                                      \
            accA[0] = fma2(w0, vj.x, accA[0]); accB[0] = fma2(w0, vj.y, accB[0]); \
            accA[1] = fma2(w1, vj.x, accA[1]); accB[1] = fma2(w1, vj.y, accB[1]); \
            accA[2] = fma2(w2, vj.x, accA[2]); accB[2] = fma2(w2, vj.y, accB[2]); \
            accA[3] = fma2(w3, vj.x, accA[3]); accB[3] = fma2(w3, vj.y, accB[3]); \
        }                                                               \
    }

    // Groups complete IN ORDER; wait_group 1 leaves only the newest pending,
    // so iteration g is guaranteed C0..Cg complete — EXCEPT the final
    // iteration, whose group is the newest: it needs wait_group 0.
    if (n == CHUNK) {
#pragma unroll 1
        for (int g = 0; g < CHUNK / 4; g++) {
            int buf = g & 1;
            if (g == CHUNK / 4 - 1) asm volatile("cp.async.wait_group 0;");
            else                    asm volatile("cp.async.wait_group 1;");
            __syncthreads();          // buffer fully landed for ALL threads
            PROCG_S(buf, g * 4, 0);
            __syncthreads();          // all reads done before refill
            if (g + 2 < CHUNK / 4) FILLG(buf, (g + 2) * 4);
        }
    } else {
        const int ngrp = (n + 3) >> 2;
#pragma unroll 1
        for (int g = 0; g < ngrp; g++) {
            int buf = g & 1;
            if (g == ngrp - 1) asm volatile("cp.async.wait_group 0;");
            else               asm volatile("cp.async.wait_group 1;");
            __syncthreads();
            PROCG_S(buf, g * 4, 1);
            __syncthreads();
            if (g + 2 < ngrp) FILLG(buf, (g + 2) * 4);
        }
    }
#undef FILLG
#undef PROCG_S

    asm volatile("cp.async.wait_all;");   // drain any tail prologue group

    // ---- write split partials (m in log2 domain; acc stored packed) ----
#pragma unroll
    for (int g = 0; g < NG; g++) {
        size_t p = (size_t)(b * NH + w * NG + g) * NSPLIT + split;
        ulonglong2 st; st.x = accA[g]; st.y = accB[g];
        *(ulonglong2*)(g_acc + p * ND + 4 * lane) = st;
    }
    if (lane < NG) {
        size_t p = (size_t)(b * NH + w * NG + lane) * NSPLIT + split;
        g_m[p] = mL; g_l[p] = lL;
    }
}

// ---------------------------------------------------------------------------
// Combine: static fully-unrolled loads (MLP=16); inactive splits zero-gated
// via msh=-1e30 (their g_acc entries are never written => zeros => 0 * 0).
// ---------------------------------------------------------------------------
__global__ __launch_bounds__(512)
void pa_combine_kernel(float* __restrict__ out, const int* __restrict__ ctx_lens)
{
    __shared__ float msh[NSPLIT], lsh[NSPLIT];
    __shared__ float osh[4][ND];

    const int bh  = blockIdx.x;          // b*NH + h
    const int tid = threadIdx.x;
    const int d   = tid & (ND - 1);
    const int j   = tid >> 7;            // 0..3

    const int ctx  = ctx_lens[bh >> 5];
    const int nact = (ctx + CHUNK - 1) >> 6;

    if (tid < NSPLIT) {
        bool a = tid < nact;
        msh[tid] = a ? g_m[(size_t)bh * NSPLIT + tid] : -1e30f;
        lsh[tid] = a ? g_l[(size_t)bh * NSPLIT + tid] : 0.f;
    }
    __syncthreads();

    float M = -1e30f;
#pragma unroll
    for (int s = 0; s < NSPLIT; s++) M = fmaxf(M, msh[s]);

    float L = 0.f;
#pragma unroll
    for (int s = 0; s < NSPLIT; s++) L += ex2(msh[s] - M) * lsh[s];

    float o = 0.f;
#pragma unroll
    for (int k = 0; k < NSPLIT / 4; k++) {
        int s = j * (NSPLIT / 4) + k;
        float f = ex2(msh[s] - M);       // exactly 0 for inactive splits
        o += f * g_acc[((size_t)bh * NSPLIT + s) * ND + d];
    }
    osh[j][d] = o;
    __syncthreads();
    if (j == 0)
        out[(size_t)bh * ND + d] =
            (osh[0][d] + osh[1][d] + osh[2][d] + osh[3][d]) / L;
}

// Empty kernel appended so ncu's fixed skip lands on pa_partial_kernel.
__global__ void pa_dummy_kernel() {}

extern "C" void kernel_launch(void* const* d_in, const int* in_sizes, int n_in,
                              void* d_out, int out_size)
{
    const float* query     = (const float*)d_in[0];
    const float* k_cache   = (const float*)d_in[1];
    const float* v_cache   = (const float*)d_in[2];
    const int*   slots     = (const int*)d_in[3];
    const int*   positions = (const int*)d_in[4];
    const int*   ctx_lens  = (const int*)d_in[5];
    float*       out       = (float*)d_out;

    static int smem_set = 0;
    if (!smem_set) {
        cudaFuncSetAttribute(pa_partial_kernel,
                             cudaFuncAttributeMaxDynamicSharedMemorySize,
                             SMEM_TOTAL);
        smem_set = 1;
    }

    dim3 grid(NSPLIT, NB);
    pa_partial_kernel<<<grid, 256, SMEM_TOTAL>>>(query, k_cache, v_cache,
                                                 slots, positions, ctx_lens);
    pa_combine_kernel<<<NB * NH, 512>>>(out, ctx_lens);
    pa_dummy_kernel<<<1, 32>>>();
}